// round 3
// baseline (speedup 1.0000x reference)
#include <cuda_runtime.h>
#include <math.h>
#include <stdint.h>

// Problem constants (fixed by dataset)
#define S_TOK   16384
#define C_DIM   1280
#define C3      3840
#define D_HEAD  80
#define H_HEADS 16
#define BLK     16
#define NBLK    (S_TOK / BLK)   // 1024

// Scratch (allocation-free rule: __device__ globals)
__device__ float g_qkv[(size_t)S_TOK * C3];    // permuted-order QKV
__device__ float g_y  [(size_t)S_TOK * C_DIM]; // attention out, ORIGINAL order

// ============================================================================
// TF32 tensor-core GEMM: C[M,N] = A[M,K] @ B[K,N]
//   mma.sync.m16n8k8.tf32 ; 128x128x16 CTA tile ; 256 thr (8 warps as 4x2)
//   warp tile 32x64 ; double-buffered smem ; vectorized fragment LDS
//   GATHER: logical A row m reads physical row gidx[m]
// ============================================================================
#define BM 128
#define BN 128
#define BK 16
#define ASTRIDE 136   // per-k row stride (u32) for A: makes LDS.64 conflict-free
#define BSTRIDE 128   // per-k row stride (u32) for B

__device__ __forceinline__ uint32_t f2tf(float f) {
    uint32_t r;
    asm("cvt.rna.tf32.f32 %0, %1;" : "=r"(r) : "f"(f));
    return r;
}

__device__ __forceinline__ void mma_tf32(float* d, const uint32_t* a, const uint32_t* b) {
    asm volatile(
        "mma.sync.aligned.m16n8k8.row.col.f32.tf32.tf32.f32 "
        "{%0,%1,%2,%3}, {%4,%5,%6,%7}, {%8,%9}, {%0,%1,%2,%3};"
        : "+f"(d[0]), "+f"(d[1]), "+f"(d[2]), "+f"(d[3])
        : "r"(a[0]), "r"(a[1]), "r"(a[2]), "r"(a[3]),
          "r"(b[0]), "r"(b[1]));
}

template<bool GATHER>
__global__ __launch_bounds__(256, 2)
void mma_gemm_kernel(const float* __restrict__ A, const float* __restrict__ B,
                     float* __restrict__ C, const int* __restrict__ gidx,
                     int M, int N, int K)
{
    // A fragment layout: As[stage][k][mt8*16 + g*2 + w]
    //   (mt8 = m/16, g = m%8, w = (m%16)/8) -> quad (w0,w1) contiguous = LDS.64
    // B fragment layout: Bs[stage][k][wn*64 + g*8 + nt]
    //   (wn = n/64, g = n%8, nt = (n%64)/8) -> 8 nt contiguous = 2x LDS.128
    __shared__ uint32_t As[2][BK][ASTRIDE];
    __shared__ uint32_t Bs[2][BK][BSTRIDE];

    const int tid  = threadIdx.x;
    const int bx   = blockIdx.x, by = blockIdx.y;
    const int warp = tid >> 5, lane = tid & 31;
    const int wm   = warp >> 1, wn = warp & 1;   // 4 x 2 warp grid
    const int g    = lane >> 2, t = lane & 3;    // mma groupID / threadID

    // ---- A global load mapping: 2 float4 / thread (rows arow, arow+64) ----
    const int arow = tid >> 2;        // 0..63
    const int ak   = (tid & 3) * 4;   // k offset of this float4 (0,4,8,12)
    int gr0 = by * BM + arow;
    int gr1 = gr0 + 64;
    if (GATHER) { gr0 = gidx[gr0]; gr1 = gidx[gr1]; }
    const float* Ap0 = A + (size_t)gr0 * K + ak;
    const float* Ap1 = A + (size_t)gr1 * K + ak;
    // smem column bases for the two A rows this thread stores
    const int ac0 = (arow >> 4) * 16 + (arow & 7) * 2 + ((arow >> 3) & 1);
    const int arow1 = arow + 64;
    const int ac1 = (arow1 >> 4) * 16 + (arow1 & 7) * 2 + ((arow1 >> 3) & 1);

    // ---- B global load mapping: 2 float4 / thread (k rows bk, bk+8) ----
    const int bk = tid >> 5;          // 0..7
    const int bn = (tid & 31) * 4;    // n offset within tile
    const float* Bp = B + (size_t)bk * N + bx * BN + bn;
    // smem columns for the 4 consecutive n values (nt fixed, g = bn%8 + i)
    const int bc0 = (bn >> 6) * 64 + (bn & 7) * 8 + ((bn >> 3) & 7);

    float acc[2][8][4];
    #pragma unroll
    for (int mt = 0; mt < 2; mt++)
        #pragma unroll
        for (int nt = 0; nt < 8; nt++)
            #pragma unroll
            for (int i = 0; i < 4; i++) acc[mt][nt][i] = 0.f;

    // ---- preload tile 0 -> stage 0 ----
    {
        float4 a0 = *(const float4*)(Ap0);
        float4 a1 = *(const float4*)(Ap1);
        float4 b0 = *(const float4*)(Bp);
        float4 b1 = *(const float4*)(Bp + (size_t)8 * N);
        As[0][ak + 0][ac0] = f2tf(a0.x);
        As[0][ak + 1][ac0] = f2tf(a0.y);
        As[0][ak + 2][ac0] = f2tf(a0.z);
        As[0][ak + 3][ac0] = f2tf(a0.w);
        As[0][ak + 0][ac1] = f2tf(a1.x);
        As[0][ak + 1][ac1] = f2tf(a1.y);
        As[0][ak + 2][ac1] = f2tf(a1.z);
        As[0][ak + 3][ac1] = f2tf(a1.w);
        Bs[0][bk][bc0 + 0 * 8]  = f2tf(b0.x);
        Bs[0][bk][bc0 + 1 * 8]  = f2tf(b0.y);
        Bs[0][bk][bc0 + 2 * 8]  = f2tf(b0.z);
        Bs[0][bk][bc0 + 3 * 8]  = f2tf(b0.w);
        Bs[0][bk + 8][bc0 + 0 * 8] = f2tf(b1.x);
        Bs[0][bk + 8][bc0 + 1 * 8] = f2tf(b1.y);
        Bs[0][bk + 8][bc0 + 2 * 8] = f2tf(b1.z);
        Bs[0][bk + 8][bc0 + 3 * 8] = f2tf(b1.w);
    }

    int s = 0;
    for (int kt = 0; kt < K; kt += BK) {
        __syncthreads();   // stage s fully written (preload or prev iter STS)

        const bool has_next = (kt + BK < K);
        float4 a0, a1, b0, b1;
        if (has_next) {
            a0 = *(const float4*)(Ap0 + kt + BK);
            a1 = *(const float4*)(Ap1 + kt + BK);
            b0 = *(const float4*)(Bp + (size_t)(kt + BK) * N);
            b1 = *(const float4*)(Bp + (size_t)(kt + BK + 8) * N);
        }

        // ---- compute on stage s ----
        #pragma unroll
        for (int ks = 0; ks < 2; ks++) {
            const int k0 = ks * 8;
            uint32_t af[2][4];
            #pragma unroll
            for (int mt = 0; mt < 2; mt++) {
                const int col = (wm * 2 + mt) * 16 + g * 2;
                // (w0,w1) pairs: LDS.64 each
                *(uint2*)&af[mt][0] = *(const uint2*)&As[s][k0 + t][col];
                *(uint2*)&af[mt][2] = *(const uint2*)&As[s][k0 + t + 4][col];
            }
            uint32_t bf0[8], bf1[8];
            {
                const int col = wn * 64 + g * 8;
                *(uint4*)&bf0[0] = *(const uint4*)&Bs[s][k0 + t][col];
                *(uint4*)&bf0[4] = *(const uint4*)&Bs[s][k0 + t][col + 4];
                *(uint4*)&bf1[0] = *(const uint4*)&Bs[s][k0 + t + 4][col];
                *(uint4*)&bf1[4] = *(const uint4*)&Bs[s][k0 + t + 4][col + 4];
            }
            #pragma unroll
            for (int mt = 0; mt < 2; mt++)
                #pragma unroll
                for (int nt = 0; nt < 8; nt++) {
                    uint32_t bb[2] = { bf0[nt], bf1[nt] };
                    mma_tf32(acc[mt][nt], af[mt], bb);
                }
        }

        // ---- stage s^1 <- prefetched regs ----
        if (has_next) {
            const int d = s ^ 1;
            As[d][ak + 0][ac0] = f2tf(a0.x);
            As[d][ak + 1][ac0] = f2tf(a0.y);
            As[d][ak + 2][ac0] = f2tf(a0.z);
            As[d][ak + 3][ac0] = f2tf(a0.w);
            As[d][ak + 0][ac1] = f2tf(a1.x);
            As[d][ak + 1][ac1] = f2tf(a1.y);
            As[d][ak + 2][ac1] = f2tf(a1.z);
            As[d][ak + 3][ac1] = f2tf(a1.w);
            Bs[d][bk][bc0 + 0 * 8]  = f2tf(b0.x);
            Bs[d][bk][bc0 + 1 * 8]  = f2tf(b0.y);
            Bs[d][bk][bc0 + 2 * 8]  = f2tf(b0.z);
            Bs[d][bk][bc0 + 3 * 8]  = f2tf(b0.w);
            Bs[d][bk + 8][bc0 + 0 * 8] = f2tf(b1.x);
            Bs[d][bk + 8][bc0 + 1 * 8] = f2tf(b1.y);
            Bs[d][bk + 8][bc0 + 2 * 8] = f2tf(b1.z);
            Bs[d][bk + 8][bc0 + 3 * 8] = f2tf(b1.w);
        }
        s ^= 1;
    }

    // ---- epilogue ----
    #pragma unroll
    for (int mt = 0; mt < 2; mt++) {
        int row0 = by * BM + wm * 32 + mt * 16 + g;
        #pragma unroll
        for (int nt = 0; nt < 8; nt++) {
            int col = bx * BN + wn * 64 + nt * 8 + t * 2;
            *(float2*)(C + (size_t)row0 * N + col) =
                make_float2(acc[mt][nt][0], acc[mt][nt][1]);
            *(float2*)(C + (size_t)(row0 + 8) * N + col) =
                make_float2(acc[mt][nt][2], acc[mt][nt][3]);
        }
    }
}

// ============================================================================
// Windowed attention with FUSED RoPE on load + inverse-permutation scatter.
// One CTA per (window block, head). 16x16 scores, D=80, fp32.
// ============================================================================
__global__ __launch_bounds__(256)
void attn_kernel(const float* __restrict__ qkv, float* __restrict__ y,
                 const int* __restrict__ win,
                 const float* __restrict__ cosp, const float* __restrict__ sinp)
{
    const int b = blockIdx.x >> 4;   // window block
    const int h = blockIdx.x & 15;   // head

    __shared__ float qs[BLK][D_HEAD + 1];
    __shared__ float ks[BLK][D_HEAD + 1];
    __shared__ float vs[BLK][D_HEAD + 1];
    __shared__ float att[BLK][BLK + 1];
    __shared__ int   toks[BLK];

    const int tid = threadIdx.x;

    if (tid < BLK) toks[tid] = win[b * BLK + tid];
    __syncthreads();

    for (int tdx = tid; tdx < BLK * D_HEAD; tdx += 256) {
        int i = tdx / D_HEAD, d = tdx % D_HEAD;
        size_t base = (size_t)(b * BLK + i) * C3 + (size_t)h * D_HEAD + d;
        float q = qkv[base];
        float k = qkv[base + C_DIM];
        float v = qkv[base + 2 * C_DIM];
        int tok = toks[i];
        float cv = cosp[(size_t)tok * D_HEAD + d];
        float sv = sinp[(size_t)tok * D_HEAD + d];
        qs[i][d] = q * cv + k * sv;
        ks[i][d] = k * cv - q * sv;
        vs[i][d] = v;
    }
    __syncthreads();

    {
        int i = tid >> 4, j = tid & 15;
        float sc = 0.f;
        #pragma unroll
        for (int d = 0; d < D_HEAD; d++) sc += qs[i][d] * ks[j][d];
        att[i][j] = sc * 0.11180339887498949f;   // 1/sqrt(80)
    }
    __syncthreads();

    if (tid < BLK) {
        float m = -1e30f;
        #pragma unroll
        for (int j = 0; j < BLK; j++) m = fmaxf(m, att[tid][j]);
        float sum = 0.f;
        #pragma unroll
        for (int j = 0; j < BLK; j++) {
            float e = __expf(att[tid][j] - m);
            att[tid][j] = e;
            sum += e;
        }
        float inv = 1.f / sum;
        #pragma unroll
        for (int j = 0; j < BLK; j++) att[tid][j] *= inv;
    }
    __syncthreads();

    for (int tdx = tid; tdx < BLK * D_HEAD; tdx += 256) {
        int i = tdx / D_HEAD, d = tdx % D_HEAD;
        float a = 0.f;
        #pragma unroll
        for (int j = 0; j < BLK; j++) a += att[i][j] * vs[j][d];
        y[(size_t)toks[i] * C_DIM + (size_t)h * D_HEAD + d] = a;
    }
}

// ============================================================================
extern "C" void kernel_launch(void* const* d_in, const int* in_sizes, int n_in,
                              void* d_out, int out_size)
{
    const float* x     = (const float*)d_in[0];
    const float* cosp  = (const float*)d_in[1];
    const float* sinp  = (const float*)d_in[2];
    const float* Wqkv  = (const float*)d_in[3];
    const float* Wproj = (const float*)d_in[4];
    const int*   win   = (const int*)  d_in[5];
    float* out = (float*)d_out;

    float *qkv_ptr, *y_ptr;
    cudaGetSymbolAddress((void**)&qkv_ptr, g_qkv);
    cudaGetSymbolAddress((void**)&y_ptr,   g_y);

    // 1) QKV GEMM with fused gather: g_qkv[s] = x[win[s]] @ W_qkv
    {
        dim3 grid(C3 / BN, S_TOK / BM);
        mma_gemm_kernel<true><<<grid, 256>>>(x, Wqkv, qkv_ptr, win,
                                             S_TOK, C3, C_DIM);
    }

    // 2) Windowed attention (RoPE fused) + inverse-permutation scatter
    {
        attn_kernel<<<NBLK * H_HEADS, 256>>>(qkv_ptr, y_ptr, win, cosp, sinp);
    }

    // 3) Output projection: out = g_y @ W_proj
    {
        dim3 grid(C_DIM / BN, S_TOK / BM);
        mma_gemm_kernel<false><<<grid, 256>>>(y_ptr, Wproj, out, nullptr,
                                              S_TOK, C_DIM, C_DIM);
    }
}

// round 5
// speedup vs baseline: 1.8168x; 1.8168x over previous
#include <cuda_runtime.h>
#include <stdint.h>

// Problem constants (fixed by dataset)
#define S_TOK   16384
#define C_DIM   1280
#define C3      3840
#define D_HEAD  80
#define BLK     16
#define NBLK    (S_TOK / BLK)   // 1024

// Scratch (__device__ globals; no allocation allowed)
__device__ float    g_qkv[(size_t)S_TOK * C3];        // permuted-order QKV (fp32)
__device__ uint32_t g_y  [(size_t)S_TOK * C_DIM];     // attention out (tf32 bits), ORIGINAL order
__device__ uint32_t g_xt [(size_t)S_TOK * C_DIM];     // x as tf32 bits
__device__ uint32_t g_wqkvT32 [(size_t)C_DIM * C3];   // W_qkv  [K,N] tf32 bits
__device__ uint32_t g_wprojT32[(size_t)C_DIM * C_DIM];// W_proj [K,N] tf32 bits

// ---------------------------------------------------------------------------
__device__ __forceinline__ uint32_t f2tf(float f) {
    uint32_t r; asm("cvt.rna.tf32.f32 %0, %1;" : "=r"(r) : "f"(f)); return r;
}
__device__ __forceinline__ uint32_t smem_u32(const void* p) {
    uint32_t a;
    asm("{ .reg .u64 t; cvta.to.shared.u64 t, %1; cvt.u32.u64 %0, t; }" : "=r"(a) : "l"(p));
    return a;
}
__device__ __forceinline__ void cpa16(uint32_t dst, const void* src) {
    asm volatile("cp.async.cg.shared.global [%0], [%1], 16;" :: "r"(dst), "l"(src) : "memory");
}
__device__ __forceinline__ void cpa_commit() {
    asm volatile("cp.async.commit_group;" ::: "memory");
}
__device__ __forceinline__ void cpa_wait1() {
    asm volatile("cp.async.wait_group 1;" ::: "memory");
}

__device__ __forceinline__ void mma_tf32(float* d, const uint32_t* a, const uint32_t* b) {
    asm volatile(
        "mma.sync.aligned.m16n8k8.row.col.f32.tf32.tf32.f32 "
        "{%0,%1,%2,%3}, {%4,%5,%6,%7}, {%8,%9}, {%0,%1,%2,%3};"
        : "+f"(d[0]), "+f"(d[1]), "+f"(d[2]), "+f"(d[3])
        : "r"(a[0]), "r"(a[1]), "r"(a[2]), "r"(a[3]),
          "r"(b[0]), "r"(b[1]));
}

// ---------------------------------------------------------------------------
// TF32 mma.sync GEMM, CTA tile 128x256, BK=16, 256 thr (8 warps as 2x4),
// warp tile 64x64 (mt=4, nt=8). 3-stage cp.async pipeline.
// A: tf32 bits [M,K] (optionally gathered rows). B: tf32 bits [K,N]. C: fp32.
// smem per stage: A [128][20]u32 = 10240B ; B [16][264]u32 = 16896B
// ---------------------------------------------------------------------------
#define BM 128
#define BN 256
#define BK 16
#define ASTR 20      // A smem row stride in words ([m][k], conflict-free 20g+t)
#define BSTR 264     // B smem row stride in words ([k][n], conflict-free 8t+g)
#define ST_A_BYTES (BM * ASTR * 4)          // 10240
#define ST_BYTES   (ST_A_BYTES + BK * BSTR * 4)  // 27136
#define NSTAGE 3
#define SMEM_BYTES (NSTAGE * ST_BYTES)      // 81408

template<bool GATHER>
__global__ __launch_bounds__(256, 1)
void mma_gemm64(const uint32_t* __restrict__ A, const uint32_t* __restrict__ B,
                float* __restrict__ C, const int* __restrict__ gidx,
                int N, int K)
{
    extern __shared__ char smem[];
    const uint32_t sb = smem_u32(smem);

    const int tid  = threadIdx.x;
    const int bx   = blockIdx.x, by = blockIdx.y;
    const int warp = tid >> 5, lane = tid & 31;
    const int wm   = warp >> 2, wn = warp & 3;   // 2 x 4 warp grid
    const int g    = lane >> 2, t = lane & 3;

    // ---- producer mapping ----
    // A: 2 rows per thread (arow, arow+64), one 16B chunk (4 k-words) each
    const int arow = tid >> 2;        // 0..63
    const int achk = tid & 3;         // 0..3
    int gm0 = by * BM + arow;
    int gm1 = gm0 + 64;
    if (GATHER) { gm0 = gidx[gm0]; gm1 = gidx[gm1]; }
    const uint32_t* Asrc0 = A + (size_t)gm0 * K + achk * 4;
    const uint32_t* Asrc1 = A + (size_t)gm1 * K + achk * 4;
    const uint32_t a_dst0 = arow * (ASTR * 4) + achk * 16;
    const uint32_t a_dst1 = (arow + 64) * (ASTR * 4) + achk * 16;
    // B: row bkrow (0..15), 4 chunks (bchk + 16j)
    const int bkrow = tid >> 4;       // 0..15
    const int bchk  = tid & 15;       // 0..15
    const uint32_t* Bsrc = B + (size_t)bkrow * N + bx * BN + bchk * 4;
    const uint32_t b_dst = ST_A_BYTES + bkrow * (BSTR * 4) + bchk * 16;

    float acc[4][8][4];
    #pragma unroll
    for (int mt = 0; mt < 4; mt++)
        #pragma unroll
        for (int nt = 0; nt < 8; nt++)
            #pragma unroll
            for (int i = 0; i < 4; i++) acc[mt][nt][i] = 0.f;

    const int NIT = K / BK;   // 80

    // ---- prologue: stages 0,1 ----
    #pragma unroll
    for (int s = 0; s < 2; s++) {
        const uint32_t so = sb + s * ST_BYTES;
        const int kt = s * BK;
        cpa16(so + a_dst0, Asrc0 + kt);
        cpa16(so + a_dst1, Asrc1 + kt);
        #pragma unroll
        for (int j = 0; j < 4; j++)
            cpa16(so + b_dst + j * 256, Bsrc + (size_t)kt * N + j * 64);
        cpa_commit();
    }

    int stage = 0;
    for (int i = 0; i < NIT; i++) {
        cpa_wait1();          // group i complete -> stage (i%3) ready
        __syncthreads();

        // issue stage i+2
        if (i + 2 < NIT) {
            const int s2 = (stage + 2 >= NSTAGE) ? stage + 2 - NSTAGE : stage + 2;
            const uint32_t so = sb + s2 * ST_BYTES;
            const int kt = (i + 2) * BK;
            cpa16(so + a_dst0, Asrc0 + kt);
            cpa16(so + a_dst1, Asrc1 + kt);
            #pragma unroll
            for (int j = 0; j < 4; j++)
                cpa16(so + b_dst + j * 256, Bsrc + (size_t)kt * N + j * 64);
        }
        cpa_commit();

        // ---- compute on current stage ----
        const uint32_t* As = (const uint32_t*)(smem + stage * ST_BYTES);
        const uint32_t* Bs = (const uint32_t*)(smem + stage * ST_BYTES + ST_A_BYTES);

        #pragma unroll
        for (int ks = 0; ks < BK; ks += 8) {
            uint32_t af[4][4];
            #pragma unroll
            for (int mt = 0; mt < 4; mt++) {
                const int m0 = wm * 64 + mt * 16 + g;
                af[mt][0] = As[m0 * ASTR + ks + t];
                af[mt][1] = As[(m0 + 8) * ASTR + ks + t];
                af[mt][2] = As[m0 * ASTR + ks + t + 4];
                af[mt][3] = As[(m0 + 8) * ASTR + ks + t + 4];
            }
            uint32_t bf[8][2];
            #pragma unroll
            for (int nt = 0; nt < 8; nt++) {
                const int n = wn * 64 + nt * 8 + g;
                bf[nt][0] = Bs[(ks + t) * BSTR + n];
                bf[nt][1] = Bs[(ks + t + 4) * BSTR + n];
            }
            #pragma unroll
            for (int mt = 0; mt < 4; mt++)
                #pragma unroll
                for (int nt = 0; nt < 8; nt++)
                    mma_tf32(acc[mt][nt], af[mt], bf[nt]);
        }

        stage = (stage + 1 == NSTAGE) ? 0 : stage + 1;
        __syncthreads();   // all reads of this stage done before its next overwrite
    }

    // ---- epilogue ----
    #pragma unroll
    for (int mt = 0; mt < 4; mt++) {
        const int row0 = by * BM + wm * 64 + mt * 16 + g;
        #pragma unroll
        for (int nt = 0; nt < 8; nt++) {
            const int col = bx * BN + wn * 64 + nt * 8 + t * 2;
            *(float2*)(C + (size_t)row0 * N + col) =
                make_float2(acc[mt][nt][0], acc[mt][nt][1]);
            *(float2*)(C + (size_t)(row0 + 8) * N + col) =
                make_float2(acc[mt][nt][2], acc[mt][nt][3]);
        }
    }
}

// ---------------------------------------------------------------------------
// Elementwise fp32 -> tf32 bits
// ---------------------------------------------------------------------------
__global__ void cvt_tf32_kernel(const float* __restrict__ in,
                                uint32_t* __restrict__ out, long n)
{
    long i = ((long)blockIdx.x * blockDim.x + threadIdx.x) * 4;
    if (i >= n) return;
    float4 f = *(const float4*)(in + i);
    uint4 u = make_uint4(f2tf(f.x), f2tf(f.y), f2tf(f.z), f2tf(f.w));
    *(uint4*)(out + i) = u;
}

// ---------------------------------------------------------------------------
// Windowed attention, RoPE fused on load, inverse-permutation scatter.
// Writes y as tf32 bits (feeds GEMM2 A directly).
// ---------------------------------------------------------------------------
__global__ __launch_bounds__(256)
void attn_kernel(const float* __restrict__ qkv, uint32_t* __restrict__ y,
                 const int* __restrict__ win,
                 const float* __restrict__ cosp, const float* __restrict__ sinp)
{
    const int b = blockIdx.x >> 4;
    const int h = blockIdx.x & 15;

    __shared__ float qs[BLK][D_HEAD + 1];
    __shared__ float ks[BLK][D_HEAD + 1];
    __shared__ float vs[BLK][D_HEAD + 1];
    __shared__ float att[BLK][BLK + 1];
    __shared__ int   toks[BLK];

    const int tid = threadIdx.x;
    if (tid < BLK) toks[tid] = win[b * BLK + tid];
    __syncthreads();

    for (int tdx = tid; tdx < BLK * D_HEAD; tdx += 256) {
        int i = tdx / D_HEAD, d = tdx % D_HEAD;
        size_t base = (size_t)(b * BLK + i) * C3 + (size_t)h * D_HEAD + d;
        float q = qkv[base];
        float k = qkv[base + C_DIM];
        float v = qkv[base + 2 * C_DIM];
        int tok = toks[i];
        float cv = cosp[(size_t)tok * D_HEAD + d];
        float sv = sinp[(size_t)tok * D_HEAD + d];
        qs[i][d] = q * cv + k * sv;
        ks[i][d] = k * cv - q * sv;
        vs[i][d] = v;
    }
    __syncthreads();

    {
        int i = tid >> 4, j = tid & 15;
        float sc = 0.f;
        #pragma unroll
        for (int d = 0; d < D_HEAD; d++) sc += qs[i][d] * ks[j][d];
        att[i][j] = sc * 0.11180339887498949f;   // 1/sqrt(80)
    }
    __syncthreads();

    if (tid < BLK) {
        float m = -1e30f;
        #pragma unroll
        for (int j = 0; j < BLK; j++) m = fmaxf(m, att[tid][j]);
        float sum = 0.f;
        #pragma unroll
        for (int j = 0; j < BLK; j++) {
            float e = __expf(att[tid][j] - m);
            att[tid][j] = e;
            sum += e;
        }
        float inv = 1.f / sum;
        #pragma unroll
        for (int j = 0; j < BLK; j++) att[tid][j] *= inv;
    }
    __syncthreads();

    for (int tdx = tid; tdx < BLK * D_HEAD; tdx += 256) {
        int i = tdx / D_HEAD, d = tdx % D_HEAD;
        float a = 0.f;
        #pragma unroll
        for (int j = 0; j < BLK; j++) a += att[i][j] * vs[j][d];
        y[(size_t)toks[i] * C_DIM + (size_t)h * D_HEAD + d] = f2tf(a);
    }
}

// ---------------------------------------------------------------------------
extern "C" void kernel_launch(void* const* d_in, const int* in_sizes, int n_in,
                              void* d_out, int out_size)
{
    const float* x     = (const float*)d_in[0];
    const float* cosp  = (const float*)d_in[1];
    const float* sinp  = (const float*)d_in[2];
    const float* Wqkv  = (const float*)d_in[3];
    const float* Wproj = (const float*)d_in[4];
    const int*   win   = (const int*)  d_in[5];
    float* out = (float*)d_out;

    float *qkv_ptr;
    uint32_t *y_ptr, *xt_ptr, *wqkv_ptr, *wproj_ptr;
    cudaGetSymbolAddress((void**)&qkv_ptr,   g_qkv);
    cudaGetSymbolAddress((void**)&y_ptr,     g_y);
    cudaGetSymbolAddress((void**)&xt_ptr,    g_xt);
    cudaGetSymbolAddress((void**)&wqkv_ptr,  g_wqkvT32);
    cudaGetSymbolAddress((void**)&wproj_ptr, g_wprojT32);

    cudaFuncSetAttribute(mma_gemm64<true>,
        cudaFuncAttributeMaxDynamicSharedMemorySize, SMEM_BYTES);
    cudaFuncSetAttribute(mma_gemm64<false>,
        cudaFuncAttributeMaxDynamicSharedMemorySize, SMEM_BYTES);

    // 0) pre-convert x and weights to tf32 bits
    {
        long nx = (long)S_TOK * C_DIM;
        cvt_tf32_kernel<<<(int)(nx / 4 / 256), 256>>>(x, xt_ptr, nx);
        long nw1 = (long)C_DIM * C3;
        cvt_tf32_kernel<<<(int)(nw1 / 4 / 256), 256>>>(Wqkv, wqkv_ptr, nw1);
        long nw2 = (long)C_DIM * C_DIM;
        cvt_tf32_kernel<<<(int)(nw2 / 4 / 256), 256>>>(Wproj, wproj_ptr, nw2);
    }

    // 1) QKV GEMM (fused gather): g_qkv[s] = x[win[s]] @ W_qkv
    {
        dim3 grid(C3 / BN, S_TOK / BM);   // 15 x 128
        mma_gemm64<true><<<grid, 256, SMEM_BYTES>>>(xt_ptr, wqkv_ptr, qkv_ptr,
                                                    win, C3, C_DIM);
    }

    // 2) Windowed attention (RoPE fused) + inverse scatter, tf32 output
    attn_kernel<<<NBLK * 16, 256>>>(qkv_ptr, y_ptr, win, cosp, sinp);

    // 3) Output projection: out = g_y @ W_proj
    {
        dim3 grid(C_DIM / BN, S_TOK / BM);  // 5 x 128
        mma_gemm64<false><<<grid, 256, SMEM_BYTES>>>(y_ptr, wproj_ptr, out,
                                                     nullptr, C_DIM, C_DIM);
    }
}

// round 6
// speedup vs baseline: 1.8834x; 1.0366x over previous
#include <cuda_runtime.h>
#include <stdint.h>

// Problem constants (fixed by dataset)
#define S_TOK   16384
#define C_DIM   1280
#define C3      3840
#define D_HEAD  80
#define BLK     16
#define NBLK    (S_TOK / BLK)   // 1024

// Scratch (__device__ globals; no allocation allowed)
__device__ float    g_qkv[(size_t)S_TOK * C3];        // permuted-order QKV (fp32)
__device__ uint32_t g_y  [(size_t)S_TOK * C_DIM];     // attention out (tf32 bits), ORIGINAL order
__device__ uint32_t g_xt [(size_t)S_TOK * C_DIM];     // x as tf32 bits
__device__ uint32_t g_wqkvT32 [(size_t)C_DIM * C3];   // W_qkv  [K,N] tf32 bits
__device__ uint32_t g_wprojT32[(size_t)C_DIM * C_DIM];// W_proj [K,N] tf32 bits

// ---------------------------------------------------------------------------
__device__ __forceinline__ uint32_t f2tf(float f) {
    uint32_t r; asm("cvt.rna.tf32.f32 %0, %1;" : "=r"(r) : "f"(f)); return r;
}
__device__ __forceinline__ uint32_t smem_u32(const void* p) {
    uint32_t a;
    asm("{ .reg .u64 t; cvta.to.shared.u64 t, %1; cvt.u32.u64 %0, t; }" : "=r"(a) : "l"(p));
    return a;
}
__device__ __forceinline__ void cpa16(uint32_t dst, const void* src) {
    asm volatile("cp.async.cg.shared.global [%0], [%1], 16;" :: "r"(dst), "l"(src) : "memory");
}
__device__ __forceinline__ void cpa_commit() {
    asm volatile("cp.async.commit_group;" ::: "memory");
}
__device__ __forceinline__ void cpa_wait2() {
    asm volatile("cp.async.wait_group 2;" ::: "memory");
}

__device__ __forceinline__ void mma_tf32(float* d, const uint32_t* a, const uint32_t* b) {
    asm volatile(
        "mma.sync.aligned.m16n8k8.row.col.f32.tf32.tf32.f32 "
        "{%0,%1,%2,%3}, {%4,%5,%6,%7}, {%8,%9}, {%0,%1,%2,%3};"
        : "+f"(d[0]), "+f"(d[1]), "+f"(d[2]), "+f"(d[3])
        : "r"(a[0]), "r"(a[1]), "r"(a[2]), "r"(a[3]),
          "r"(b[0]), "r"(b[1]));
}

// ---------------------------------------------------------------------------
// TF32 mma.sync GEMM, CTA tile 128x128, BK=16, 128 thr (4 warps as 2x2),
// warp tile 64x64 (mt=4, nt=8). 4-stage cp.async pipeline, ONE sync/iter,
// 2 CTAs per SM for cross-CTA latency hiding.
// A: tf32 bits [M,K] (optional row gather). B: tf32 bits [K,N]. C: fp32.
// smem/stage: A [128][20]u32 = 10240B ; B [16][136]u32 = 8704B -> 18944B
// ---------------------------------------------------------------------------
#define BM 128
#define BN 128
#define BK 16
#define ASTR 20      // A [m][k] row stride (words): LDS banks 20g+t, all distinct
#define BSTR 136     // B [k][n] row stride (words): 136%32=8 -> banks 8t+g, distinct
#define ST_A_BYTES (BM * ASTR * 4)               // 10240
#define ST_BYTES   (ST_A_BYTES + BK * BSTR * 4)  // 18944
#define NSTAGE 4
#define SMEM_BYTES (NSTAGE * ST_BYTES)           // 75776

template<bool GATHER>
__global__ __launch_bounds__(128, 2)
void mma_gemm64(const uint32_t* __restrict__ A, const uint32_t* __restrict__ B,
                float* __restrict__ C, const int* __restrict__ gidx,
                int N, int K)
{
    extern __shared__ char smem[];
    const uint32_t sb = smem_u32(smem);

    const int tid  = threadIdx.x;
    const int bx   = blockIdx.x, by = blockIdx.y;
    const int warp = tid >> 5, lane = tid & 31;
    const int wm   = warp >> 1, wn = warp & 1;   // 2 x 2 warp grid
    const int g    = lane >> 2, t = lane & 3;

    // ---- producer mapping (128 threads) ----
    // A: 4 rows per thread (arow + 32j), one 16B chunk (achk) each
    const int arow = tid >> 2;        // 0..31
    const int achk = tid & 3;         // 0..3
    const uint32_t* Asrc[4];
    uint32_t a_dst[4];
    #pragma unroll
    for (int j = 0; j < 4; j++) {
        int m = by * BM + arow + 32 * j;
        int gm = GATHER ? gidx[m] : m;
        Asrc[j] = A + (size_t)gm * K + achk * 4;
        a_dst[j] = (arow + 32 * j) * (ASTR * 4) + achk * 16;
    }
    // B: row bkrow (0..15), chunks bchk + 8j (j=0..3)
    const int bkrow = tid >> 3;       // 0..15
    const int bchk  = tid & 7;        // 0..7
    const uint32_t* Bsrc = B + (size_t)bkrow * N + bx * BN + bchk * 4;
    const uint32_t b_dst = ST_A_BYTES + bkrow * (BSTR * 4) + bchk * 16;

    float acc[4][8][4];
    #pragma unroll
    for (int mt = 0; mt < 4; mt++)
        #pragma unroll
        for (int nt = 0; nt < 8; nt++)
            #pragma unroll
            for (int i = 0; i < 4; i++) acc[mt][nt][i] = 0.f;

    const int NIT = K / BK;   // 80

    // ---- prologue: issue stages 0..2 ----
    #pragma unroll
    for (int s = 0; s < NSTAGE - 1; s++) {
        const uint32_t so = sb + s * ST_BYTES;
        const int kt = s * BK;
        #pragma unroll
        for (int j = 0; j < 4; j++) cpa16(so + a_dst[j], Asrc[j] + kt);
        #pragma unroll
        for (int j = 0; j < 4; j++)
            cpa16(so + b_dst + j * 128, Bsrc + (size_t)kt * N + j * 32);
        cpa_commit();
    }

    int stage = 0;
    for (int i = 0; i < NIT; i++) {
        cpa_wait2();          // groups 0..i complete -> stage i%4 ready
        __syncthreads();      // visibility + all reads of stage (i-1)%4 done

        // issue tile i+3 into stage (i+3)%4 == (i-1)%4 (safe: fenced above)
        if (i + NSTAGE - 1 < NIT) {
            int s3 = stage + (NSTAGE - 1);
            if (s3 >= NSTAGE) s3 -= NSTAGE;
            const uint32_t so = sb + s3 * ST_BYTES;
            const int kt = (i + NSTAGE - 1) * BK;
            #pragma unroll
            for (int j = 0; j < 4; j++) cpa16(so + a_dst[j], Asrc[j] + kt);
            #pragma unroll
            for (int j = 0; j < 4; j++)
                cpa16(so + b_dst + j * 128, Bsrc + (size_t)kt * N + j * 32);
        }
        cpa_commit();         // (possibly empty group; keeps wait counts aligned)

        // ---- compute on current stage ----
        const uint32_t* As = (const uint32_t*)(smem + stage * ST_BYTES);
        const uint32_t* Bs = (const uint32_t*)(smem + stage * ST_BYTES + ST_A_BYTES);

        #pragma unroll
        for (int ks = 0; ks < BK; ks += 8) {
            uint32_t af[4][4];
            #pragma unroll
            for (int mt = 0; mt < 4; mt++) {
                const int m0 = wm * 64 + mt * 16 + g;
                af[mt][0] = As[m0 * ASTR + ks + t];
                af[mt][1] = As[(m0 + 8) * ASTR + ks + t];
                af[mt][2] = As[m0 * ASTR + ks + t + 4];
                af[mt][3] = As[(m0 + 8) * ASTR + ks + t + 4];
            }
            uint32_t bf[8][2];
            #pragma unroll
            for (int nt = 0; nt < 8; nt++) {
                const int n = wn * 64 + nt * 8 + g;
                bf[nt][0] = Bs[(ks + t) * BSTR + n];
                bf[nt][1] = Bs[(ks + t + 4) * BSTR + n];
            }
            #pragma unroll
            for (int mt = 0; mt < 4; mt++)
                #pragma unroll
                for (int nt = 0; nt < 8; nt++)
                    mma_tf32(acc[mt][nt], af[mt], bf[nt]);
        }

        stage = (stage + 1 == NSTAGE) ? 0 : stage + 1;
    }

    // ---- epilogue ----
    #pragma unroll
    for (int mt = 0; mt < 4; mt++) {
        const int row0 = by * BM + wm * 64 + mt * 16 + g;
        #pragma unroll
        for (int nt = 0; nt < 8; nt++) {
            const int col = bx * BN + wn * 64 + nt * 8 + t * 2;
            *(float2*)(C + (size_t)row0 * N + col) =
                make_float2(acc[mt][nt][0], acc[mt][nt][1]);
            *(float2*)(C + (size_t)(row0 + 8) * N + col) =
                make_float2(acc[mt][nt][2], acc[mt][nt][3]);
        }
    }
}

// ---------------------------------------------------------------------------
// Elementwise fp32 -> tf32 bits
// ---------------------------------------------------------------------------
__global__ void cvt_tf32_kernel(const float* __restrict__ in,
                                uint32_t* __restrict__ out, long n)
{
    long i = ((long)blockIdx.x * blockDim.x + threadIdx.x) * 4;
    if (i >= n) return;
    float4 f = *(const float4*)(in + i);
    uint4 u = make_uint4(f2tf(f.x), f2tf(f.y), f2tf(f.z), f2tf(f.w));
    *(uint4*)(out + i) = u;
}

// ---------------------------------------------------------------------------
// Windowed attention, RoPE fused on load, inverse-permutation scatter.
// Writes y as tf32 bits (feeds GEMM2 A directly).
// ---------------------------------------------------------------------------
__global__ __launch_bounds__(256)
void attn_kernel(const float* __restrict__ qkv, uint32_t* __restrict__ y,
                 const int* __restrict__ win,
                 const float* __restrict__ cosp, const float* __restrict__ sinp)
{
    const int b = blockIdx.x >> 4;
    const int h = blockIdx.x & 15;

    __shared__ float qs[BLK][D_HEAD + 1];
    __shared__ float ks[BLK][D_HEAD + 1];
    __shared__ float vs[BLK][D_HEAD + 1];
    __shared__ float att[BLK][BLK + 1];
    __shared__ int   toks[BLK];

    const int tid = threadIdx.x;
    if (tid < BLK) toks[tid] = win[b * BLK + tid];
    __syncthreads();

    for (int tdx = tid; tdx < BLK * D_HEAD; tdx += 256) {
        int i = tdx / D_HEAD, d = tdx % D_HEAD;
        size_t base = (size_t)(b * BLK + i) * C3 + (size_t)h * D_HEAD + d;
        float q = qkv[base];
        float k = qkv[base + C_DIM];
        float v = qkv[base + 2 * C_DIM];
        int tok = toks[i];
        float cv = cosp[(size_t)tok * D_HEAD + d];
        float sv = sinp[(size_t)tok * D_HEAD + d];
        qs[i][d] = q * cv + k * sv;
        ks[i][d] = k * cv - q * sv;
        vs[i][d] = v;
    }
    __syncthreads();

    {
        int i = tid >> 4, j = tid & 15;
        float sc = 0.f;
        #pragma unroll
        for (int d = 0; d < D_HEAD; d++) sc += qs[i][d] * ks[j][d];
        att[i][j] = sc * 0.11180339887498949f;   // 1/sqrt(80)
    }
    __syncthreads();

    if (tid < BLK) {
        float m = -1e30f;
        #pragma unroll
        for (int j = 0; j < BLK; j++) m = fmaxf(m, att[tid][j]);
        float sum = 0.f;
        #pragma unroll
        for (int j = 0; j < BLK; j++) {
            float e = __expf(att[tid][j] - m);
            att[tid][j] = e;
            sum += e;
        }
        float inv = 1.f / sum;
        #pragma unroll
        for (int j = 0; j < BLK; j++) att[tid][j] *= inv;
    }
    __syncthreads();

    for (int tdx = tid; tdx < BLK * D_HEAD; tdx += 256) {
        int i = tdx / D_HEAD, d = tdx % D_HEAD;
        float a = 0.f;
        #pragma unroll
        for (int j = 0; j < BLK; j++) a += att[i][j] * vs[j][d];
        y[(size_t)toks[i] * C_DIM + (size_t)h * D_HEAD + d] = f2tf(a);
    }
}

// ---------------------------------------------------------------------------
extern "C" void kernel_launch(void* const* d_in, const int* in_sizes, int n_in,
                              void* d_out, int out_size)
{
    const float* x     = (const float*)d_in[0];
    const float* cosp  = (const float*)d_in[1];
    const float* sinp  = (const float*)d_in[2];
    const float* Wqkv  = (const float*)d_in[3];
    const float* Wproj = (const float*)d_in[4];
    const int*   win   = (const int*)  d_in[5];
    float* out = (float*)d_out;

    float *qkv_ptr;
    uint32_t *y_ptr, *xt_ptr, *wqkv_ptr, *wproj_ptr;
    cudaGetSymbolAddress((void**)&qkv_ptr,   g_qkv);
    cudaGetSymbolAddress((void**)&y_ptr,     g_y);
    cudaGetSymbolAddress((void**)&xt_ptr,    g_xt);
    cudaGetSymbolAddress((void**)&wqkv_ptr,  g_wqkvT32);
    cudaGetSymbolAddress((void**)&wproj_ptr, g_wprojT32);

    cudaFuncSetAttribute(mma_gemm64<true>,
        cudaFuncAttributeMaxDynamicSharedMemorySize, SMEM_BYTES);
    cudaFuncSetAttribute(mma_gemm64<false>,
        cudaFuncAttributeMaxDynamicSharedMemorySize, SMEM_BYTES);

    // 0) pre-convert x and weights to tf32 bits
    {
        long nx = (long)S_TOK * C_DIM;
        cvt_tf32_kernel<<<(int)(nx / 4 / 256), 256>>>(x, xt_ptr, nx);
        long nw1 = (long)C_DIM * C3;
        cvt_tf32_kernel<<<(int)(nw1 / 4 / 256), 256>>>(Wqkv, wqkv_ptr, nw1);
        long nw2 = (long)C_DIM * C_DIM;
        cvt_tf32_kernel<<<(int)(nw2 / 4 / 256), 256>>>(Wproj, wproj_ptr, nw2);
    }

    // 1) QKV GEMM (fused gather): g_qkv[s] = x[win[s]] @ W_qkv
    {
        dim3 grid(C3 / BN, S_TOK / BM);   // 30 x 128
        mma_gemm64<true><<<grid, 128, SMEM_BYTES>>>(xt_ptr, wqkv_ptr, qkv_ptr,
                                                    win, C3, C_DIM);
    }

    // 2) Windowed attention (RoPE fused) + inverse scatter, tf32 output
    attn_kernel<<<NBLK * 16, 256>>>(qkv_ptr, y_ptr, win, cosp, sinp);

    // 3) Output projection: out = g_y @ W_proj
    {
        dim3 grid(C_DIM / BN, S_TOK / BM);  // 10 x 128
        mma_gemm64<false><<<grid, 128, SMEM_BYTES>>>(y_ptr, wproj_ptr, out,
                                                     nullptr, C_DIM, C_DIM);
    }
}

// round 7
// speedup vs baseline: 1.8856x; 1.0011x over previous
#include <cuda_runtime.h>
#include <stdint.h>

// Problem constants (fixed by dataset)
#define S_TOK   16384
#define C_DIM   1280
#define C3      3840
#define D_HEAD  80
#define BLK     16
#define NBLK    (S_TOK / BLK)   // 1024

// Scratch (__device__ globals; no allocation allowed)
__device__ float    g_qkv[(size_t)S_TOK * C3];        // permuted-order QKV (fp32)
__device__ uint32_t g_y  [(size_t)S_TOK * C_DIM];     // attention out (tf32 bits), ORIGINAL order
__device__ uint32_t g_xt [(size_t)S_TOK * C_DIM];     // x as tf32 bits
__device__ uint32_t g_wqkvT32 [(size_t)C_DIM * C3];   // W_qkv  [K,N] tf32 bits
__device__ uint32_t g_wprojT32[(size_t)C_DIM * C_DIM];// W_proj [K,N] tf32 bits

// ---------------------------------------------------------------------------
__device__ __forceinline__ uint32_t f2tf(float f) {
    uint32_t r; asm("cvt.rna.tf32.f32 %0, %1;" : "=r"(r) : "f"(f)); return r;
}
__device__ __forceinline__ uint32_t smem_u32(const void* p) {
    uint32_t a;
    asm("{ .reg .u64 t; cvta.to.shared.u64 t, %1; cvt.u32.u64 %0, t; }" : "=r"(a) : "l"(p));
    return a;
}
__device__ __forceinline__ void cpa16(uint32_t dst, const void* src) {
    asm volatile("cp.async.cg.shared.global [%0], [%1], 16;" :: "r"(dst), "l"(src) : "memory");
}
__device__ __forceinline__ void cpa_commit() {
    asm volatile("cp.async.commit_group;" ::: "memory");
}
__device__ __forceinline__ void cpa_wait1() {
    asm volatile("cp.async.wait_group 1;" ::: "memory");
}

__device__ __forceinline__ void mma_tf32(float* d, const uint32_t* a, const uint32_t* b) {
    asm volatile(
        "mma.sync.aligned.m16n8k8.row.col.f32.tf32.tf32.f32 "
        "{%0,%1,%2,%3}, {%4,%5,%6,%7}, {%8,%9}, {%0,%1,%2,%3};"
        : "+f"(d[0]), "+f"(d[1]), "+f"(d[2]), "+f"(d[3])
        : "r"(a[0]), "r"(a[1]), "r"(a[2]), "r"(a[3]),
          "r"(b[0]), "r"(b[1]));
}

// ---------------------------------------------------------------------------
// TF32 mma.sync GEMM, CTA tile 128x128, BK=32, 128 thr (4 warps as 2x2),
// warp tile 64x64. 3-stage cp.async pipeline, 1 sync per BK=32 iter,
// fragment double-buffer hides LDS latency, 2 CTAs/SM.
// A: tf32 bits [M,K] (optional row gather). B: tf32 bits [K,N]. C: fp32.
// smem/stage: A [128][36]u32 = 18432B ; B [32][136]u32 = 17408B -> 35840B
// ---------------------------------------------------------------------------
#define BM 128
#define BN 128
#define BK 32
#define ASTR 36      // A [m][k] stride (words): frag banks 4g+t+ks, all distinct
#define BSTR 136     // B [k][n] stride (words): frag banks 8t+g, all distinct
#define ST_A_BYTES (BM * ASTR * 4)               // 18432
#define ST_BYTES   (ST_A_BYTES + BK * BSTR * 4)  // 35840
#define NSTAGE 3
#define SMEM_BYTES (NSTAGE * ST_BYTES)           // 107520

template<bool GATHER>
__global__ __launch_bounds__(128, 2)
void mma_gemm64(const uint32_t* __restrict__ A, const uint32_t* __restrict__ B,
                float* __restrict__ C, const int* __restrict__ gidx,
                int N, int K)
{
    extern __shared__ char smem[];
    const uint32_t sb = smem_u32(smem);

    const int tid  = threadIdx.x;
    const int bx   = blockIdx.x, by = blockIdx.y;
    const int warp = tid >> 5, lane = tid & 31;
    const int wm   = warp >> 1, wn = warp & 1;   // 2 x 2 warp grid
    const int g    = lane >> 2, t = lane & 3;

    // ---- producer mapping (128 threads, BK=32 => 128B per A row) ----
    // A: rows arow+32j (j=0..3), chunks achk & achk+4  -> 8 cpa16 / thread
    const int arow = tid >> 2;        // 0..31
    const int achk = tid & 3;         // 0..3
    const uint32_t* Asrc[4];
    uint32_t a_dst[4];
    #pragma unroll
    for (int j = 0; j < 4; j++) {
        int m = by * BM + arow + 32 * j;
        int gm = GATHER ? gidx[m] : m;
        Asrc[j] = A + (size_t)gm * K;
        a_dst[j] = (arow + 32 * j) * (ASTR * 4);
    }
    // B: rows (tid>>5)+4c (c=0..7), chunk tid&31  -> 8 cpa16 / thread
    const int brow0 = tid >> 5;       // 0..3
    const int bchk  = tid & 31;       // 0..31
    const uint32_t* Bsrc = B + (size_t)brow0 * N + bx * BN + bchk * 4;
    const uint32_t b_dst = ST_A_BYTES + brow0 * (BSTR * 4) + bchk * 16;

    float acc[4][8][4];
    #pragma unroll
    for (int mt = 0; mt < 4; mt++)
        #pragma unroll
        for (int nt = 0; nt < 8; nt++)
            #pragma unroll
            for (int i = 0; i < 4; i++) acc[mt][nt][i] = 0.f;

    const int NIT = K / BK;   // 40

    // ---- prologue: issue stages 0,1 ----
    #pragma unroll
    for (int s = 0; s < NSTAGE - 1; s++) {
        const uint32_t so = sb + s * ST_BYTES;
        const int kt = s * BK;
        #pragma unroll
        for (int j = 0; j < 4; j++) {
            cpa16(so + a_dst[j] + achk * 16,       Asrc[j] + kt + achk * 4);
            cpa16(so + a_dst[j] + (achk + 4) * 16, Asrc[j] + kt + (achk + 4) * 4);
        }
        #pragma unroll
        for (int c = 0; c < 8; c++)
            cpa16(so + b_dst + c * (4 * BSTR * 4),
                  Bsrc + (size_t)(kt + 4 * c) * N);
        cpa_commit();
    }

    int stage = 0;
    for (int i = 0; i < NIT; i++) {
        cpa_wait1();          // group i complete -> stage i%3 ready
        __syncthreads();      // + all reads of stage (i-1)%3 finished

        // issue tile i+2 into stage (i+2)%3 == (i-1)%3
        if (i + NSTAGE - 1 < NIT) {
            int s2 = stage + (NSTAGE - 1);
            if (s2 >= NSTAGE) s2 -= NSTAGE;
            const uint32_t so = sb + s2 * ST_BYTES;
            const int kt = (i + NSTAGE - 1) * BK;
            #pragma unroll
            for (int j = 0; j < 4; j++) {
                cpa16(so + a_dst[j] + achk * 16,       Asrc[j] + kt + achk * 4);
                cpa16(so + a_dst[j] + (achk + 4) * 16, Asrc[j] + kt + (achk + 4) * 4);
            }
            #pragma unroll
            for (int c = 0; c < 8; c++)
                cpa16(so + b_dst + c * (4 * BSTR * 4),
                      Bsrc + (size_t)(kt + 4 * c) * N);
        }
        cpa_commit();

        // ---- compute on current stage: 4 k8 steps, frag double-buffer ----
        const uint32_t* As = (const uint32_t*)(smem + stage * ST_BYTES);
        const uint32_t* Bs = (const uint32_t*)(smem + stage * ST_BYTES + ST_A_BYTES);

        uint32_t af[2][4][4], bf[2][8][2];
        // load step 0
        #pragma unroll
        for (int mt = 0; mt < 4; mt++) {
            const int m0 = wm * 64 + mt * 16 + g;
            af[0][mt][0] = As[m0 * ASTR + t];
            af[0][mt][1] = As[(m0 + 8) * ASTR + t];
            af[0][mt][2] = As[m0 * ASTR + t + 4];
            af[0][mt][3] = As[(m0 + 8) * ASTR + t + 4];
        }
        #pragma unroll
        for (int nt = 0; nt < 8; nt++) {
            const int n = wn * 64 + nt * 8 + g;
            bf[0][nt][0] = Bs[t * BSTR + n];
            bf[0][nt][1] = Bs[(t + 4) * BSTR + n];
        }

        #pragma unroll
        for (int s8 = 0; s8 < 4; s8++) {
            const int cur = s8 & 1, nxt = cur ^ 1;
            if (s8 < 3) {
                const int ks = (s8 + 1) * 8;
                #pragma unroll
                for (int mt = 0; mt < 4; mt++) {
                    const int m0 = wm * 64 + mt * 16 + g;
                    af[nxt][mt][0] = As[m0 * ASTR + ks + t];
                    af[nxt][mt][1] = As[(m0 + 8) * ASTR + ks + t];
                    af[nxt][mt][2] = As[m0 * ASTR + ks + t + 4];
                    af[nxt][mt][3] = As[(m0 + 8) * ASTR + ks + t + 4];
                }
                #pragma unroll
                for (int nt = 0; nt < 8; nt++) {
                    const int n = wn * 64 + nt * 8 + g;
                    bf[nxt][nt][0] = Bs[(ks + t) * BSTR + n];
                    bf[nxt][nt][1] = Bs[(ks + t + 4) * BSTR + n];
                }
            }
            #pragma unroll
            for (int mt = 0; mt < 4; mt++)
                #pragma unroll
                for (int nt = 0; nt < 8; nt++)
                    mma_tf32(acc[mt][nt], af[cur][mt], bf[cur][nt]);
        }

        stage = (stage + 1 == NSTAGE) ? 0 : stage + 1;
    }

    // ---- epilogue ----
    #pragma unroll
    for (int mt = 0; mt < 4; mt++) {
        const int row0 = by * BM + wm * 64 + mt * 16 + g;
        #pragma unroll
        for (int nt = 0; nt < 8; nt++) {
            const int col = bx * BN + wn * 64 + nt * 8 + t * 2;
            *(float2*)(C + (size_t)row0 * N + col) =
                make_float2(acc[mt][nt][0], acc[mt][nt][1]);
            *(float2*)(C + (size_t)(row0 + 8) * N + col) =
                make_float2(acc[mt][nt][2], acc[mt][nt][3]);
        }
    }
}

// ---------------------------------------------------------------------------
// Elementwise fp32 -> tf32 bits
// ---------------------------------------------------------------------------
__global__ void cvt_tf32_kernel(const float* __restrict__ in,
                                uint32_t* __restrict__ out, long n)
{
    long i = ((long)blockIdx.x * blockDim.x + threadIdx.x) * 4;
    if (i >= n) return;
    float4 f = *(const float4*)(in + i);
    uint4 u = make_uint4(f2tf(f.x), f2tf(f.y), f2tf(f.z), f2tf(f.w));
    *(uint4*)(out + i) = u;
}

// ---------------------------------------------------------------------------
// Windowed attention, RoPE fused on load, inverse-permutation scatter.
// Writes y as tf32 bits (feeds GEMM2 A directly).
// ---------------------------------------------------------------------------
__global__ __launch_bounds__(256)
void attn_kernel(const float* __restrict__ qkv, uint32_t* __restrict__ y,
                 const int* __restrict__ win,
                 const float* __restrict__ cosp, const float* __restrict__ sinp)
{
    const int b = blockIdx.x >> 4;
    const int h = blockIdx.x & 15;

    __shared__ float qs[BLK][D_HEAD + 1];
    __shared__ float ks[BLK][D_HEAD + 1];
    __shared__ float vs[BLK][D_HEAD + 1];
    __shared__ float att[BLK][BLK + 1];
    __shared__ int   toks[BLK];

    const int tid = threadIdx.x;
    if (tid < BLK) toks[tid] = win[b * BLK + tid];
    __syncthreads();

    for (int tdx = tid; tdx < BLK * D_HEAD; tdx += 256) {
        int i = tdx / D_HEAD, d = tdx % D_HEAD;
        size_t base = (size_t)(b * BLK + i) * C3 + (size_t)h * D_HEAD + d;
        float q = qkv[base];
        float k = qkv[base + C_DIM];
        float v = qkv[base + 2 * C_DIM];
        int tok = toks[i];
        float cv = cosp[(size_t)tok * D_HEAD + d];
        float sv = sinp[(size_t)tok * D_HEAD + d];
        qs[i][d] = q * cv + k * sv;
        ks[i][d] = k * cv - q * sv;
        vs[i][d] = v;
    }
    __syncthreads();

    {
        int i = tid >> 4, j = tid & 15;
        float sc = 0.f;
        #pragma unroll
        for (int d = 0; d < D_HEAD; d++) sc += qs[i][d] * ks[j][d];
        att[i][j] = sc * 0.11180339887498949f;   // 1/sqrt(80)
    }
    __syncthreads();

    if (tid < BLK) {
        float m = -1e30f;
        #pragma unroll
        for (int j = 0; j < BLK; j++) m = fmaxf(m, att[tid][j]);
        float sum = 0.f;
        #pragma unroll
        for (int j = 0; j < BLK; j++) {
            float e = __expf(att[tid][j] - m);
            att[tid][j] = e;
            sum += e;
        }
        float inv = 1.f / sum;
        #pragma unroll
        for (int j = 0; j < BLK; j++) att[tid][j] *= inv;
    }
    __syncthreads();

    for (int tdx = tid; tdx < BLK * D_HEAD; tdx += 256) {
        int i = tdx / D_HEAD, d = tdx % D_HEAD;
        float a = 0.f;
        #pragma unroll
        for (int j = 0; j < BLK; j++) a += att[i][j] * vs[j][d];
        y[(size_t)toks[i] * C_DIM + (size_t)h * D_HEAD + d] = f2tf(a);
    }
}

// ---------------------------------------------------------------------------
extern "C" void kernel_launch(void* const* d_in, const int* in_sizes, int n_in,
                              void* d_out, int out_size)
{
    const float* x     = (const float*)d_in[0];
    const float* cosp  = (const float*)d_in[1];
    const float* sinp  = (const float*)d_in[2];
    const float* Wqkv  = (const float*)d_in[3];
    const float* Wproj = (const float*)d_in[4];
    const int*   win   = (const int*)  d_in[5];
    float* out = (float*)d_out;

    float *qkv_ptr;
    uint32_t *y_ptr, *xt_ptr, *wqkv_ptr, *wproj_ptr;
    cudaGetSymbolAddress((void**)&qkv_ptr,   g_qkv);
    cudaGetSymbolAddress((void**)&y_ptr,     g_y);
    cudaGetSymbolAddress((void**)&xt_ptr,    g_xt);
    cudaGetSymbolAddress((void**)&wqkv_ptr,  g_wqkvT32);
    cudaGetSymbolAddress((void**)&wproj_ptr, g_wprojT32);

    cudaFuncSetAttribute(mma_gemm64<true>,
        cudaFuncAttributeMaxDynamicSharedMemorySize, SMEM_BYTES);
    cudaFuncSetAttribute(mma_gemm64<false>,
        cudaFuncAttributeMaxDynamicSharedMemorySize, SMEM_BYTES);

    // 0) pre-convert x and weights to tf32 bits
    {
        long nx = (long)S_TOK * C_DIM;
        cvt_tf32_kernel<<<(int)(nx / 4 / 256), 256>>>(x, xt_ptr, nx);
        long nw1 = (long)C_DIM * C3;
        cvt_tf32_kernel<<<(int)(nw1 / 4 / 256), 256>>>(Wqkv, wqkv_ptr, nw1);
        long nw2 = (long)C_DIM * C_DIM;
        cvt_tf32_kernel<<<(int)(nw2 / 4 / 256), 256>>>(Wproj, wproj_ptr, nw2);
    }

    // 1) QKV GEMM (fused gather): g_qkv[s] = x[win[s]] @ W_qkv
    {
        dim3 grid(C3 / BN, S_TOK / BM);   // 30 x 128
        mma_gemm64<true><<<grid, 128, SMEM_BYTES>>>(xt_ptr, wqkv_ptr, qkv_ptr,
                                                    win, C3, C_DIM);
    }

    // 2) Windowed attention (RoPE fused) + inverse scatter, tf32 output
    attn_kernel<<<NBLK * 16, 256>>>(qkv_ptr, y_ptr, win, cosp, sinp);

    // 3) Output projection: out = g_y @ W_proj
    {
        dim3 grid(C_DIM / BN, S_TOK / BM);  // 10 x 128
        mma_gemm64<false><<<grid, 128, SMEM_BYTES>>>(y_ptr, wproj_ptr, out,
                                                     nullptr, C_DIM, C_DIM);
    }
}